// round 5
// baseline (speedup 1.0000x reference)
#include <cuda_runtime.h>
#include <cuda_bf16.h>
#include <math.h>

#define NROWS 8192
#define DDIM  512
#define NG    64
#define MAXG  512

// Scratch (device globals: allocation-free rule)
__device__ float g_q[NROWS * DDIM];
__device__ float g_k[NROWS * DDIM];
__device__ float g_v[NROWS * DDIM];
__device__ float g_att[NROWS * DDIM];
__device__ int   g_cnt[NG];
__device__ int   g_mem[NG * MAXG];

// ---------------------------------------------------------------------------
// Zero helpers
// ---------------------------------------------------------------------------
__global__ void zero_cnt_kernel() {
    if (threadIdx.x < NG) g_cnt[threadIdx.x] = 0;
}

__global__ void zero_att_kernel() {
    int i = blockIdx.x * blockDim.x + threadIdx.x;       // float4 index
    ((float4*)g_att)[i] = make_float4(0.f, 0.f, 0.f, 0.f);
}

// ---------------------------------------------------------------------------
// Build per-group member lists
// ---------------------------------------------------------------------------
__global__ void build_groups_kernel(const int* __restrict__ labels) {
    int i = blockIdx.x * blockDim.x + threadIdx.x;
    if (i < NROWS) {
        int lb = labels[i];
        if (lb >= 0) {
            int pos = atomicAdd(&g_cnt[lb], 1);
            if (pos < MAXG) g_mem[lb * MAXG + pos] = i;
        }
    }
}

// ---------------------------------------------------------------------------
// SGEMM: C[M,512] = A[M,512] @ W[512,512] + bias  (fp32, 128x128x16 tiles)
// grid = (512/128, M/128), block = 256, 8x8 per thread
// ---------------------------------------------------------------------------
__global__ __launch_bounds__(256)
void gemm_bias_kernel(const float* __restrict__ A,
                      const float* __restrict__ W,
                      const float* __restrict__ bias,
                      float* __restrict__ C) {
    const int K = DDIM;
    __shared__ float As[16][128];
    __shared__ float Ws[16][128];

    const int tid = threadIdx.x;
    const int tx = tid & 15;
    const int ty = tid >> 4;
    const int rowBase = blockIdx.y * 128;
    const int colBase = blockIdx.x * 128;

    float acc[8][8];
#pragma unroll
    for (int i = 0; i < 8; i++)
#pragma unroll
        for (int j = 0; j < 8; j++) acc[i][j] = 0.f;

    for (int k0 = 0; k0 < K; k0 += 16) {
        // A tile: 128 rows x 16 cols  (512 float4 loads, 2 per thread), store transposed
#pragma unroll
        for (int s = 0; s < 2; s++) {
            int idx = tid * 2 + s;
            int r = idx >> 2;
            int c = (idx & 3) * 4;
            float4 f = *(const float4*)&A[(size_t)(rowBase + r) * K + k0 + c];
            As[c + 0][r] = f.x;
            As[c + 1][r] = f.y;
            As[c + 2][r] = f.z;
            As[c + 3][r] = f.w;
        }
        // W tile: 16 rows x 128 cols
#pragma unroll
        for (int s = 0; s < 2; s++) {
            int idx = tid * 2 + s;
            int r = idx >> 5;
            int c = (idx & 31) * 4;
            float4 f = *(const float4*)&W[(size_t)(k0 + r) * DDIM + colBase + c];
            *(float4*)&Ws[r][c] = f;
        }
        __syncthreads();

#pragma unroll
        for (int kk = 0; kk < 16; kk++) {
            float a[8], b[8];
            *(float4*)&a[0] = *(float4*)&As[kk][ty * 8];
            *(float4*)&a[4] = *(float4*)&As[kk][ty * 8 + 4];
            *(float4*)&b[0] = *(float4*)&Ws[kk][tx * 8];
            *(float4*)&b[4] = *(float4*)&Ws[kk][tx * 8 + 4];
#pragma unroll
            for (int i = 0; i < 8; i++)
#pragma unroll
                for (int j = 0; j < 8; j++)
                    acc[i][j] = fmaf(a[i], b[j], acc[i][j]);
        }
        __syncthreads();
    }

    // epilogue + bias
#pragma unroll
    for (int i = 0; i < 8; i++) {
        int row = rowBase + ty * 8 + i;
#pragma unroll
        for (int j = 0; j < 8; j += 4) {
            int col = colBase + tx * 8 + j;
            float4 o;
            o.x = acc[i][j + 0] + bias[col + 0];
            o.y = acc[i][j + 1] + bias[col + 1];
            o.z = acc[i][j + 2] + bias[col + 2];
            o.w = acc[i][j + 3] + bias[col + 3];
            *(float4*)&C[(size_t)row * DDIM + col] = o;
        }
    }
}

// ---------------------------------------------------------------------------
// Per-group flash-style attention.
// grid = (NG, 8), block = 256 (8 warps). Each warp owns 2 query rows of the
// group at a time; K/V staged in 128KB dynamic smem tiles of TK=32 keys.
// ---------------------------------------------------------------------------
#define TK 32
#define QCHUNK 16         // q rows per block pass (8 warps x 2)
#define YSPLIT 8

__global__ __launch_bounds__(256)
void attn_kernel() {
    extern __shared__ float smem[];            // ks[TK*DDIM] | vs[TK*DDIM]
    float* ks = smem;
    float* vs = smem + TK * DDIM;

    const int g = blockIdx.x;
    const int m = g_cnt[g];
    if (m == 0) return;
    if ((int)(blockIdx.y * QCHUNK) >= m && blockIdx.y * QCHUNK >= m) {
        // still fall through to the loop; loop handles bounds
    }

    const int tid  = threadIdx.x;
    const int warp = tid >> 5;
    const int lane = tid & 31;
    const int* mem = &g_mem[g * MAXG];
    const float scale = 0.044194173824159216f;   // 1/sqrt(512)

    for (int qbase = blockIdx.y * QCHUNK; qbase < m; qbase += QCHUNK * YSPLIT) {
        const int qi0 = qbase + warp * 2;
        int row0 = (qi0     < m) ? mem[qi0]     : -1;
        int row1 = (qi0 + 1 < m) ? mem[qi0 + 1] : -1;

        float q0[16], q1[16], a0[16], a1[16];
#pragma unroll
        for (int jj = 0; jj < 16; jj++) { q0[jj] = 0.f; q1[jj] = 0.f; a0[jj] = 0.f; a1[jj] = 0.f; }
        if (row0 >= 0) {
#pragma unroll
            for (int jj = 0; jj < 16; jj++) q0[jj] = g_q[(size_t)row0 * DDIM + lane + 32 * jj];
        }
        if (row1 >= 0) {
#pragma unroll
            for (int jj = 0; jj < 16; jj++) q1[jj] = g_q[(size_t)row1 * DDIM + lane + 32 * jj];
        }
        float m0 = -1e30f, l0 = 0.f;
        float m1 = -1e30f, l1 = 0.f;

        for (int kt = 0; kt < m; kt += TK) {
            const int tkn = min(TK, m - kt);
            __syncthreads();
            // cooperative gather of K/V tile (float4 per thread-iter)
            for (int t = tid; t < TK * (DDIM / 4); t += 256) {
                int j  = t >> 7;          // key within tile
                int c4 = t & 127;         // float4 column
                if (j < tkn) {
                    size_t src = (size_t)mem[kt + j] * DDIM + c4 * 4;
                    *(float4*)&ks[j * DDIM + c4 * 4] = *(const float4*)&g_k[src];
                    *(float4*)&vs[j * DDIM + c4 * 4] = *(const float4*)&g_v[src];
                }
            }
            __syncthreads();

            if (row0 >= 0) {                       // warp-uniform
                for (int j = 0; j < tkn; j++) {
                    const float* kr = &ks[j * DDIM];
                    float s0 = 0.f, s1 = 0.f;
#pragma unroll
                    for (int jj = 0; jj < 16; jj++) {
                        float kv = kr[lane + 32 * jj];
                        s0 = fmaf(q0[jj], kv, s0);
                        s1 = fmaf(q1[jj], kv, s1);
                    }
#pragma unroll
                    for (int o = 16; o; o >>= 1) {
                        s0 += __shfl_xor_sync(0xffffffffu, s0, o);
                        s1 += __shfl_xor_sync(0xffffffffu, s1, o);
                    }
                    s0 *= scale;
                    s1 *= scale;
                    const float* vr = &vs[j * DDIM];
                    {
                        float mn   = fmaxf(m0, s0);
                        float corr = __expf(m0 - mn);
                        float p    = __expf(s0 - mn);
                        l0 = l0 * corr + p;
#pragma unroll
                        for (int jj = 0; jj < 16; jj++)
                            a0[jj] = fmaf(p, vr[lane + 32 * jj], a0[jj] * corr);
                        m0 = mn;
                    }
                    if (row1 >= 0) {
                        float mn   = fmaxf(m1, s1);
                        float corr = __expf(m1 - mn);
                        float p    = __expf(s1 - mn);
                        l1 = l1 * corr + p;
#pragma unroll
                        for (int jj = 0; jj < 16; jj++)
                            a1[jj] = fmaf(p, vr[lane + 32 * jj], a1[jj] * corr);
                        m1 = mn;
                    }
                }
            }
        }

        if (row0 >= 0) {
            float inv = 1.f / l0;
#pragma unroll
            for (int jj = 0; jj < 16; jj++)
                g_att[(size_t)row0 * DDIM + lane + 32 * jj] = a0[jj] * inv;
        }
        if (row1 >= 0) {
            float inv = 1.f / l1;
#pragma unroll
            for (int jj = 0; jj < 16; jj++)
                g_att[(size_t)row1 * DDIM + lane + 32 * jj] = a1[jj] * inv;
        }
        __syncthreads();   // protect smem before next pass overwrites
    }
}

// ---------------------------------------------------------------------------
// Launch
// ---------------------------------------------------------------------------
extern "C" void kernel_launch(void* const* d_in, const int* in_sizes, int n_in,
                              void* d_out, int out_size) {
    const float* x      = (const float*)d_in[0];
    const int*   labels = (const int*)  d_in[1];
    const float* Wq     = (const float*)d_in[2];
    const float* bq     = (const float*)d_in[3];
    const float* Wk     = (const float*)d_in[4];
    const float* bk     = (const float*)d_in[5];
    const float* Wv     = (const float*)d_in[6];
    const float* bv     = (const float*)d_in[7];
    const float* Wo     = (const float*)d_in[8];
    const float* bo     = (const float*)d_in[9];
    float* out = (float*)d_out;

    float *q, *k, *v, *att;
    cudaGetSymbolAddress((void**)&q,   g_q);
    cudaGetSymbolAddress((void**)&k,   g_k);
    cudaGetSymbolAddress((void**)&v,   g_v);
    cudaGetSymbolAddress((void**)&att, g_att);

    zero_cnt_kernel<<<1, 64>>>();
    zero_att_kernel<<<(NROWS * DDIM / 4) / 256, 256>>>();
    build_groups_kernel<<<NROWS / 256, 256>>>(labels);

    dim3 ggrid(DDIM / 128, NROWS / 128);
    gemm_bias_kernel<<<ggrid, 256>>>(x, Wq, bq, q);
    gemm_bias_kernel<<<ggrid, 256>>>(x, Wk, bk, k);
    gemm_bias_kernel<<<ggrid, 256>>>(x, Wv, bv, v);

    const int smem_bytes = 2 * TK * DDIM * sizeof(float);   // 128 KB
    cudaFuncSetAttribute(attn_kernel, cudaFuncAttributeMaxDynamicSharedMemorySize, smem_bytes);
    attn_kernel<<<dim3(NG, YSPLIT), 256, smem_bytes>>>();

    gemm_bias_kernel<<<ggrid, 256>>>(att, Wo, bo, out);
}

// round 7
// speedup vs baseline: 1.9084x; 1.9084x over previous
#include <cuda_runtime.h>
#include <cuda_bf16.h>
#include <mma.h>
#include <math.h>
#include <stdint.h>

using namespace nvcuda;

#define NROWS 8192
#define DDIM  512
#define NG    64
#define MAXG  512

// ---------------------------------------------------------------------------
// Scratch (device globals: allocation-free rule)
// ---------------------------------------------------------------------------
__device__ float g_q[NROWS * DDIM];
__device__ float g_k[NROWS * DDIM];
__device__ float g_v[NROWS * DDIM];
__device__ float g_att[NROWS * DDIM];
__device__ int   g_cnt[NG];
__device__ int   g_mem[NG * MAXG];

// bf16 split operands (g_xh/g_xl reused for att split after QKV GEMMs)
__device__ __nv_bfloat16 g_xh[NROWS * DDIM];
__device__ __nv_bfloat16 g_xl[NROWS * DDIM];
// 4 split weights (row-major, NOT transposed): [w][k*512+n]
__device__ __nv_bfloat16 g_wh[4 * DDIM * DDIM];
__device__ __nv_bfloat16 g_wl[4 * DDIM * DDIM];
// 4 broadcast bias tiles: [w][16][512] (16 identical rows each)
__device__ float g_btile[4 * 16 * DDIM];

// ---------------------------------------------------------------------------
// Small kernels
// ---------------------------------------------------------------------------
__global__ void zero_cnt_kernel() {
    if (threadIdx.x < NG) g_cnt[threadIdx.x] = 0;
}

__global__ void zero_att_kernel() {
    int i = blockIdx.x * blockDim.x + threadIdx.x;
    ((float4*)g_att)[i] = make_float4(0.f, 0.f, 0.f, 0.f);
}

__global__ void build_groups_kernel(const int* __restrict__ labels) {
    int i = blockIdx.x * blockDim.x + threadIdx.x;
    if (i < NROWS) {
        int lb = labels[i];
        if (lb >= 0) {
            int pos = atomicAdd(&g_cnt[lb], 1);
            if (pos < MAXG) g_mem[lb * MAXG + pos] = i;
        }
    }
}

// fp32 -> (bf16 hi, bf16 lo) elementwise split, float4 vectorized
__global__ void split_kernel(const float* __restrict__ src,
                             __nv_bfloat16* __restrict__ hi,
                             __nv_bfloat16* __restrict__ lo) {
    int i = blockIdx.x * blockDim.x + threadIdx.x;      // float4 index
    float4 f = ((const float4*)src)[i];
    __nv_bfloat16 h0 = __float2bfloat16(f.x);
    __nv_bfloat16 h1 = __float2bfloat16(f.y);
    __nv_bfloat16 h2 = __float2bfloat16(f.z);
    __nv_bfloat16 h3 = __float2bfloat16(f.w);
    __nv_bfloat16 l0 = __float2bfloat16(f.x - __bfloat162float(h0));
    __nv_bfloat16 l1 = __float2bfloat16(f.y - __bfloat162float(h1));
    __nv_bfloat16 l2 = __float2bfloat16(f.z - __bfloat162float(h2));
    __nv_bfloat16 l3 = __float2bfloat16(f.w - __bfloat162float(h3));
    __nv_bfloat162* ph = (__nv_bfloat162*)hi;
    __nv_bfloat162* pl = (__nv_bfloat162*)lo;
    ph[i * 2 + 0] = __nv_bfloat162(h0, h1);
    ph[i * 2 + 1] = __nv_bfloat162(h2, h3);
    pl[i * 2 + 0] = __nv_bfloat162(l0, l1);
    pl[i * 2 + 1] = __nv_bfloat162(l2, l3);
}

// Build 4 broadcast bias tiles [16][512]
__global__ void bias_tile_kernel(const float* __restrict__ bq,
                                 const float* __restrict__ bk,
                                 const float* __restrict__ bv,
                                 const float* __restrict__ bo) {
    int i = blockIdx.x * blockDim.x + threadIdx.x;   // 0 .. 4*16*512-1
    int w   = i >> 13;                               // /(16*512)
    int col = i & (DDIM - 1);
    const float* b = (w == 0) ? bq : (w == 1) ? bk : (w == 2) ? bv : bo;
    g_btile[i] = b[col];
}

// ---------------------------------------------------------------------------
// WMMA bf16-split GEMM: C[8192,512] = A @ W + bias (fp32-accurate)
// A as (Ah, Al) [M,512] row-major; B as (Bh, Bl) [512,512] row-major (= W).
// grid = (DDIM/128, M/128), block = 256 (8 warps, 2x4), warp tile 64x32.
// acc initialized from broadcast bias tile => bias folded in for free.
// ---------------------------------------------------------------------------
#define KC    32
#define LDA   48     // KC + 16 pad  (96B row stride, 32B-aligned)
#define LDB   144    // 128 + 16 pad (288B row stride, 32B-aligned)

__global__ __launch_bounds__(256)
void wmma_gemm_kernel(const __nv_bfloat16* __restrict__ Ah,
                      const __nv_bfloat16* __restrict__ Al,
                      const __nv_bfloat16* __restrict__ Bh,
                      const __nv_bfloat16* __restrict__ Bl,
                      const float* __restrict__ btile,  // [16][512]
                      float* __restrict__ C) {
    __shared__ __nv_bfloat16 sAh[128][LDA];
    __shared__ __nv_bfloat16 sAl[128][LDA];
    __shared__ __nv_bfloat16 sBh[KC][LDB];
    __shared__ __nv_bfloat16 sBl[KC][LDB];

    const int tid = threadIdx.x;
    const int wid = tid >> 5;
    const int warpRow = wid & 1;        // 0..1  -> 64-row slab
    const int warpCol = wid >> 1;       // 0..3  -> 32-col slab
    const int rowBase = blockIdx.y * 128;
    const int colBase = blockIdx.x * 128;
    const int wRow = warpRow * 64;      // within CTA tile
    const int wCol = warpCol * 32;

    wmma::fragment<wmma::accumulator, 16, 16, 16, float> acc[4][2];
#pragma unroll
    for (int mi = 0; mi < 4; mi++)
#pragma unroll
        for (int ni = 0; ni < 2; ni++)
            wmma::load_matrix_sync(acc[mi][ni],
                                   btile + (colBase + wCol + ni * 16),
                                   DDIM, wmma::mem_row_major);

    for (int kc = 0; kc < DDIM; kc += KC) {
        // stage A (128x32) hi/lo: 4096 bf16 each; 2 x uint4 per thread
#pragma unroll
        for (int s = 0; s < 2; s++) {
            int idx = tid * 2 + s;            // 0..511
            int r = idx >> 2;                 // 0..127
            int c = (idx & 3) * 8;            // 0,8,16,24
            size_t ga = (size_t)(rowBase + r) * DDIM + kc + c;
            *(uint4*)&sAh[r][c] = *(const uint4*)(Ah + ga);
            *(uint4*)&sAl[r][c] = *(const uint4*)(Al + ga);
        }
        // stage B (32x128) hi/lo
#pragma unroll
        for (int s = 0; s < 2; s++) {
            int idx = tid * 2 + s;            // 0..511
            int r = idx >> 4;                 // 0..31
            int c = (idx & 15) * 8;           // 0..120
            size_t gb = (size_t)(kc + r) * DDIM + colBase + c;
            *(uint4*)&sBh[r][c] = *(const uint4*)(Bh + gb);
            *(uint4*)&sBl[r][c] = *(const uint4*)(Bl + gb);
        }
        __syncthreads();

#pragma unroll
        for (int k16 = 0; k16 < KC; k16 += 16) {
            wmma::fragment<wmma::matrix_a, 16, 16, 16, __nv_bfloat16, wmma::row_major> ah[4], al[4];
            wmma::fragment<wmma::matrix_b, 16, 16, 16, __nv_bfloat16, wmma::row_major> bh[2], bl[2];
#pragma unroll
            for (int mi = 0; mi < 4; mi++) {
                wmma::load_matrix_sync(ah[mi], &sAh[wRow + mi * 16][k16], LDA);
                wmma::load_matrix_sync(al[mi], &sAl[wRow + mi * 16][k16], LDA);
            }
#pragma unroll
            for (int ni = 0; ni < 2; ni++) {
                wmma::load_matrix_sync(bh[ni], &sBh[k16][wCol + ni * 16], LDB);
                wmma::load_matrix_sync(bl[ni], &sBl[k16][wCol + ni * 16], LDB);
            }
#pragma unroll
            for (int mi = 0; mi < 4; mi++)
#pragma unroll
                for (int ni = 0; ni < 2; ni++) {
                    wmma::mma_sync(acc[mi][ni], ah[mi], bh[ni], acc[mi][ni]);
                    wmma::mma_sync(acc[mi][ni], ah[mi], bl[ni], acc[mi][ni]);
                    wmma::mma_sync(acc[mi][ni], al[mi], bh[ni], acc[mi][ni]);
                }
        }
        __syncthreads();
    }

    // epilogue: direct store (bias already in acc)
#pragma unroll
    for (int mi = 0; mi < 4; mi++)
#pragma unroll
        for (int ni = 0; ni < 2; ni++)
            wmma::store_matrix_sync(
                &C[(size_t)(rowBase + wRow + mi * 16) * DDIM + colBase + wCol + ni * 16],
                acc[mi][ni], DDIM, wmma::mem_row_major);
}

// ---------------------------------------------------------------------------
// Per-group flash-style attention (unchanged from R5 passing kernel)
// ---------------------------------------------------------------------------
#define TK 32
#define QCHUNK 16
#define YSPLIT 8

__global__ __launch_bounds__(256)
void attn_kernel() {
    extern __shared__ float smemf[];
    float* ks = smemf;
    float* vs = smemf + TK * DDIM;

    const int g = blockIdx.x;
    const int m = g_cnt[g];
    if (m == 0) return;

    const int tid  = threadIdx.x;
    const int warp = tid >> 5;
    const int lane = tid & 31;
    const int* mem = &g_mem[g * MAXG];
    const float scale = 0.044194173824159216f;   // 1/sqrt(512)

    for (int qbase = blockIdx.y * QCHUNK; qbase < m; qbase += QCHUNK * YSPLIT) {
        const int qi0 = qbase + warp * 2;
        int row0 = (qi0     < m) ? mem[qi0]     : -1;
        int row1 = (qi0 + 1 < m) ? mem[qi0 + 1] : -1;

        float q0[16], q1[16], a0[16], a1[16];
#pragma unroll
        for (int jj = 0; jj < 16; jj++) { q0[jj] = 0.f; q1[jj] = 0.f; a0[jj] = 0.f; a1[jj] = 0.f; }
        if (row0 >= 0) {
#pragma unroll
            for (int jj = 0; jj < 16; jj++) q0[jj] = g_q[(size_t)row0 * DDIM + lane + 32 * jj];
        }
        if (row1 >= 0) {
#pragma unroll
            for (int jj = 0; jj < 16; jj++) q1[jj] = g_q[(size_t)row1 * DDIM + lane + 32 * jj];
        }
        float m0 = -1e30f, l0 = 0.f;
        float m1 = -1e30f, l1 = 0.f;

        for (int kt = 0; kt < m; kt += TK) {
            const int tkn = min(TK, m - kt);
            __syncthreads();
            for (int t = tid; t < TK * (DDIM / 4); t += 256) {
                int j  = t >> 7;
                int c4 = t & 127;
                if (j < tkn) {
                    size_t src = (size_t)mem[kt + j] * DDIM + c4 * 4;
                    *(float4*)&ks[j * DDIM + c4 * 4] = *(const float4*)&g_k[src];
                    *(float4*)&vs[j * DDIM + c4 * 4] = *(const float4*)&g_v[src];
                }
            }
            __syncthreads();

            if (row0 >= 0) {
                for (int j = 0; j < tkn; j++) {
                    const float* kr = &ks[j * DDIM];
                    float s0 = 0.f, s1 = 0.f;
#pragma unroll
                    for (int jj = 0; jj < 16; jj++) {
                        float kv = kr[lane + 32 * jj];
                        s0 = fmaf(q0[jj], kv, s0);
                        s1 = fmaf(q1[jj], kv, s1);
                    }
#pragma unroll
                    for (int o = 16; o; o >>= 1) {
                        s0 += __shfl_xor_sync(0xffffffffu, s0, o);
                        s1 += __shfl_xor_sync(0xffffffffu, s1, o);
                    }
                    s0 *= scale;
                    s1 *= scale;
                    const float* vr = &vs[j * DDIM];
                    {
                        float mn   = fmaxf(m0, s0);
                        float corr = __expf(m0 - mn);
                        float p    = __expf(s0 - mn);
                        l0 = l0 * corr + p;
#pragma unroll
                        for (int jj = 0; jj < 16; jj++)
                            a0[jj] = fmaf(p, vr[lane + 32 * jj], a0[jj] * corr);
                        m0 = mn;
                    }
                    if (row1 >= 0) {
                        float mn   = fmaxf(m1, s1);
                        float corr = __expf(m1 - mn);
                        float p    = __expf(s1 - mn);
                        l1 = l1 * corr + p;
#pragma unroll
                        for (int jj = 0; jj < 16; jj++)
                            a1[jj] = fmaf(p, vr[lane + 32 * jj], a1[jj] * corr);
                        m1 = mn;
                    }
                }
            }
        }

        if (row0 >= 0) {
            float inv = 1.f / l0;
#pragma unroll
            for (int jj = 0; jj < 16; jj++)
                g_att[(size_t)row0 * DDIM + lane + 32 * jj] = a0[jj] * inv;
        }
        if (row1 >= 0) {
            float inv = 1.f / l1;
#pragma unroll
            for (int jj = 0; jj < 16; jj++)
                g_att[(size_t)row1 * DDIM + lane + 32 * jj] = a1[jj] * inv;
        }
        __syncthreads();
    }
}

// ---------------------------------------------------------------------------
// Launch
// ---------------------------------------------------------------------------
extern "C" void kernel_launch(void* const* d_in, const int* in_sizes, int n_in,
                              void* d_out, int out_size) {
    const float* x      = (const float*)d_in[0];
    const int*   labels = (const int*)  d_in[1];
    const float* Wq     = (const float*)d_in[2];
    const float* bq     = (const float*)d_in[3];
    const float* Wk     = (const float*)d_in[4];
    const float* bk     = (const float*)d_in[5];
    const float* Wv     = (const float*)d_in[6];
    const float* bv     = (const float*)d_in[7];
    const float* Wo     = (const float*)d_in[8];
    const float* bo     = (const float*)d_in[9];
    float* out = (float*)d_out;

    float *q, *k, *v, *att, *btile;
    __nv_bfloat16 *xh, *xl, *wh, *wl;
    cudaGetSymbolAddress((void**)&q,     g_q);
    cudaGetSymbolAddress((void**)&k,     g_k);
    cudaGetSymbolAddress((void**)&v,     g_v);
    cudaGetSymbolAddress((void**)&att,   g_att);
    cudaGetSymbolAddress((void**)&xh,    g_xh);
    cudaGetSymbolAddress((void**)&xl,    g_xl);
    cudaGetSymbolAddress((void**)&wh,    g_wh);
    cudaGetSymbolAddress((void**)&wl,    g_wl);
    cudaGetSymbolAddress((void**)&btile, g_btile);

    static bool attr_done = false;
    if (!attr_done) {
        cudaFuncSetAttribute(attn_kernel,
                             cudaFuncAttributeMaxDynamicSharedMemorySize,
                             2 * TK * DDIM * (int)sizeof(float));
        attr_done = true;
    }

    zero_cnt_kernel<<<1, 64>>>();
    zero_att_kernel<<<(NROWS * DDIM / 4) / 256, 256>>>();
    build_groups_kernel<<<NROWS / 256, 256>>>(labels);

    // split x; split all 4 weights (row-major, no transpose needed for WMMA)
    split_kernel<<<(NROWS * DDIM / 4) / 256, 256>>>(x, xh, xl);
    const int WSZ = DDIM * DDIM;
    split_kernel<<<(WSZ / 4) / 256, 256>>>(Wq, wh + 0 * WSZ, wl + 0 * WSZ);
    split_kernel<<<(WSZ / 4) / 256, 256>>>(Wk, wh + 1 * WSZ, wl + 1 * WSZ);
    split_kernel<<<(WSZ / 4) / 256, 256>>>(Wv, wh + 2 * WSZ, wl + 2 * WSZ);
    split_kernel<<<(WSZ / 4) / 256, 256>>>(Wo, wh + 3 * WSZ, wl + 3 * WSZ);
    bias_tile_kernel<<<(4 * 16 * DDIM) / 256, 256>>>(bq, bk, bv, bo);

    dim3 ggrid(DDIM / 128, NROWS / 128);
    const int BT = 16 * DDIM;
    wmma_gemm_kernel<<<ggrid, 256>>>(xh, xl, wh + 0 * WSZ, wl + 0 * WSZ, btile + 0 * BT, q);
    wmma_gemm_kernel<<<ggrid, 256>>>(xh, xl, wh + 1 * WSZ, wl + 1 * WSZ, btile + 1 * BT, k);
    wmma_gemm_kernel<<<ggrid, 256>>>(xh, xl, wh + 2 * WSZ, wl + 2 * WSZ, btile + 2 * BT, v);

    const int attn_smem = 2 * TK * DDIM * (int)sizeof(float);   // 128 KB
    attn_kernel<<<dim3(NG, YSPLIT), 256, attn_smem>>>();

    // reuse xh/xl for att split, then output GEMM straight into d_out
    split_kernel<<<(NROWS * DDIM / 4) / 256, 256>>>(att, xh, xl);
    wmma_gemm_kernel<<<ggrid, 256>>>(xh, xl, wh + 3 * WSZ, wl + 3 * WSZ, btile + 3 * BT, out);
}